// round 16
// baseline (speedup 1.0000x reference)
#include <cuda_runtime.h>
#include <cuda_bf16.h>

// Problem constants (fixed by dataset: feats [8,64,32,32], N boxes)
#define B_    8
#define C_    64
#define H_    32
#define W_    32
#define HOUT  8
#define WOUT  8

#define WXP   36              // WxT row pitch (floats): 144B, 16B-aligned, bank step 4
#define OYP   36              // s_tmp oy pitch (floats)
#define CLP   296             // s_tmp channel pitch (floats): 1184B, 16B-aligned

#define NMAX  4096
#define NBLK  592             // 148 SMs x 4 blocks: exactly one wave

#define FMA2(d, a, b, c) asm("fma.rn.f32x2 %0, %1, %2, %3;" : "=l"(d) : "l"(a), "l"(b), "l"(c))
#define PACK2(d, lo, hi) asm("mov.b64 %0, {%1, %2};" : "=l"(d) : "f"(lo), "f"(hi))
#define UNPK2(lo, hi, s) asm("mov.b64 {%0, %1}, %2;" : "=f"(lo), "=f"(hi) : "l"(s))

// Per-box precomputed weights (prep kernel -> main kernel)
__device__ unsigned long long g_Wy2[NMAX * 256];      // [n][y*8+oy], packed {w,w}
__device__ float              g_WxT[NMAX * 8 * WXP];  // [n][ox][x]
__device__ int                g_hdr[NMAX * 8];        // xc0,ncx,case,b,ylo_pack,cnt_pack
__device__ int                g_ctr;                  // work-stealing counter

// ---------------------------------------------------------------------------
// Prep kernel: 4 boxes per 256-thread block; 64 threads per box.
// Also initializes the work-stealing counter for the persistent roi kernel.
// ---------------------------------------------------------------------------
__global__ void prep_kernel(const int* __restrict__ batch_idxs,
                            const int* __restrict__ starts,
                            const int* __restrict__ goals, int N, int nblk) {
    const int tid = threadIdx.x;
    const int bl  = tid >> 6;
    const int sub = tid & 63;
    const int n   = blockIdx.x * 4 + bl;

    if (blockIdx.x == 0 && tid == 0) g_ctr = nblk;   // next work item after wave-0

    __shared__ float s_Wy[4][H_ * 8];
    __shared__ float s_Wx[4][8 * WXP];

    for (int k = sub; k < H_ * 8;  k += 64) s_Wy[bl][k] = 0.0f;
    for (int k = sub; k < 8 * WXP; k += 64) s_Wx[bl][k] = 0.0f;
    __syncthreads();

    if (n < N) {
        const float sy = (float)starts[2 * n + 0];
        const float sx = (float)starts[2 * n + 1];
        const float gy = (float)goals[2 * n + 0];
        const float gx = (float)goals[2 * n + 1];
        const float y_min = fminf(sy, gy), y_max = fmaxf(sy, gy);
        const float x_min = fminf(sx, gx), x_max = fmaxf(sx, gx);

        const float start_h = y_min - 0.5f;
        const float start_w = x_min - 0.5f;
        const float bin_h = (y_max - y_min) / (float)HOUT;
        const float bin_w = (x_max - x_min) / (float)WOUT;
        const int gh = (int)ceilf(bin_h);
        const int gw = (int)ceilf(bin_w);
        const float invc = 1.0f / (float)max(gh * gw, 1);

        const int axis = sub >> 5;            // 0 = y, 1 = x
        const int idx  = sub & 31;
        const int ph   = idx >> 2;
        const int i    = idx & 3;

        const float start  = axis ? start_w : start_h;
        const float bin_sz = axis ? bin_w  : bin_h;
        const int   grid   = axis ? gw     : gh;
        const float size   = 32.0f;

        const float g_safe = fmaxf((float)grid, 1.0f);
        const float pos    = start + (float)ph * bin_sz
                           + ((float)i + 0.5f) * (bin_sz / g_safe);
        const bool  valid  = (pos >= -1.0f) && (pos <= size) && (i < grid);
        const float p      = fminf(fmaxf(pos, 0.0f), size - 1.0f);
        const float lowf   = floorf(p);
        const int   low    = (int)lowf;
        const int   high   = min(low + 1, (int)size - 1);
        const float l      = p - lowf;
        const float vf     = valid ? 1.0f : 0.0f;

        if (axis == 0) {
            atomicAdd(&s_Wy[bl][low  * 8 + ph], (1.0f - l) * vf * invc);
            atomicAdd(&s_Wy[bl][high * 8 + ph], l * vf * invc);
        } else {
            atomicAdd(&s_Wx[bl][ph * WXP + low ], (1.0f - l) * vf);
            atomicAdd(&s_Wx[bl][ph * WXP + high], l * vf);
        }

        if (sub == 0) {
            g_hdr[n * 8 + 2] = ((sy > gy) ? 2 : 0) + ((sx > gx) ? 1 : 0);
            g_hdr[n * 8 + 3] = batch_idxs[n];
        }
    }
    __syncthreads();

    if (n < N) {
        if (sub < 32) {
            // per-bin-pair y starts + per-GROUP shared row counts
            const int yr = sub;               // lane = y row
            int ylo[4], cnt[4];
            #pragma unroll
            for (int pp = 0; pp < 4; pp++) {
                const bool nz = (s_Wy[bl][yr * 8 + 2 * pp]     != 0.0f) ||
                                (s_Wy[bl][yr * 8 + 2 * pp + 1] != 0.0f);
                unsigned m = __ballot_sync(0xffffffffu, nz);
                ylo[pp] = m ? (__ffs(m) - 1) : 0;
                cnt[pp] = m ? (32 - __clz(m)) - ylo[pp] : 0;
            }
            if (sub == 0) {
                const int cn0 = max(max(cnt[0], cnt[1]), 1);
                const int cn1 = max(max(cnt[2], cnt[3]), 1);
                unsigned ylop = 0;
                ylop |= (unsigned)min(ylo[0], H_ - cn0);
                ylop |= (unsigned)min(ylo[1], H_ - cn0) << 8;
                ylop |= (unsigned)min(ylo[2], H_ - cn1) << 16;
                ylop |= (unsigned)min(ylo[3], H_ - cn1) << 24;
                g_hdr[n * 8 + 4] = (int)ylop;
                g_hdr[n * 8 + 5] = cn0 | (cn1 << 8);
            }
        } else {
            const int lane = sub - 32;
            float s = 0.0f;
            #pragma unroll
            for (int ox = 0; ox < 8; ox++) s += s_Wx[bl][ox * WXP + lane];
            unsigned m = __ballot_sync(0xffffffffu, s != 0.0f);
            if (lane == 0) {
                if (m) {
                    const int x0  = __ffs(m) - 1;
                    const int x1  = 32 - __clz(m);          // exclusive
                    const int xc0 = x0 & ~3;
                    g_hdr[n * 8 + 0] = xc0;
                    g_hdr[n * 8 + 1] = (x1 - xc0 + 3) >> 2;
                } else { g_hdr[n * 8 + 0] = 0; g_hdr[n * 8 + 1] = 0; }
            }
        }
        for (int k = sub; k < H_ * 8; k += 64) {
            const float w = s_Wy[bl][k];
            unsigned long long pw;
            PACK2(pw, w, w);
            g_Wy2[n * 256 + k] = pw;
        }
        for (int k = sub; k < 8 * WXP; k += 64)
            g_WxT[n * 8 * WXP + k] = s_Wx[bl][k];
    }
}

// ---------------------------------------------------------------------------
// Main kernel: PERSISTENT blocks (one wave) with dynamic work-stealing over
// (box, half) items. Per item: weight copy + barrier, warp-private pass A
// (2 loops x 2 interleaved bin-pairs, MLP 4), pass B with flip fast path.
// ---------------------------------------------------------------------------
__global__ __launch_bounds__(256, 4)
void roi_kernel(const float* __restrict__ feats, float* __restrict__ out,
                int total_work) {
    const int tid = threadIdx.x;

    __shared__ unsigned long long s_Wy2[H_ * 8];   // packed {w,w}
    __shared__ float s_WxT[8 * WXP];               // [ox][x]
    __shared__ float s_tmp[32 * CLP];              // [cl][oy][x]
    __shared__ int   s_next;

#if __CUDA_ARCH__ >= 900
    cudaGridDependencySynchronize();               // PDL: wait for prep results
#endif

    const int warp = tid >> 5;
    const int lane = tid & 31;

    int wid = blockIdx.x;
    while (wid < total_work) {
        const int n = wid >> 1;
        const int h = wid & 1;

        // coalesced weight copy
        s_Wy2[tid] = g_Wy2[n * 256 + tid];
        if (tid < 8 * WXP)        s_WxT[tid]       = g_WxT[n * 8 * WXP + tid];
        if (tid < 8 * WXP - 256)  s_WxT[256 + tid] = g_WxT[n * 8 * WXP + 256 + tid];

        const int xc0  = __ldg(&g_hdr[n * 8 + 0]);
        const int ncx  = __ldg(&g_hdr[n * 8 + 1]);
        const int cse  = __ldg(&g_hdr[n * 8 + 2]);
        const int b    = __ldg(&g_hdr[n * 8 + 3]);
        const unsigned ylop = (unsigned)__ldg(&g_hdr[n * 8 + 4]);
        const int      cntp = __ldg(&g_hdr[n * 8 + 5]);
        __syncthreads();

        // ---- Pass A: tmp[cl][oy][x] = sum_y Wy[y][oy] * f[c][y][x] ----
        {
            const int cc = lane >> 3;             // channel within warp (0..3)
            const int xg = lane & 7;              // x group (4 floats)
            const int cl = warp * 4 + cc;
            const int c  = h * 32 + cl;

            const ulonglong2* __restrict__ fp = (const ulonglong2*)
                (feats + (size_t)(b * C_ + c) * (H_ * W_)) + xg;
            float* tp = s_tmp + cl * CLP + 4 * xg;

            #pragma unroll
            for (int g = 0; g < 2; g++) {
                const int ylA = (int)((ylop >> (g * 16))     & 0xFF);
                const int ylB = (int)((ylop >> (g * 16 + 8)) & 0xFF);
                const int cn  = (cntp >> (g * 8)) & 0xFF;

                const ulonglong2* fqA = fp + (size_t)ylA * 8;
                const ulonglong2* fqB = fp + (size_t)ylB * 8;

                unsigned long long acc[8];
                #pragma unroll
                for (int k = 0; k < 8; k++) acc[k] = 0ull;

                #pragma unroll 2
                for (int t = 0; t < cn; t++) {
                    const ulonglong2 vA = __ldg(fqA + (size_t)t * 8);
                    const ulonglong2 vB = __ldg(fqB + (size_t)t * 8);
                    const ulonglong2 wA =
                        *(const ulonglong2*)&s_Wy2[(ylA + t) * 8 + 4 * g];
                    const ulonglong2 wB =
                        *(const ulonglong2*)&s_Wy2[(ylB + t) * 8 + 4 * g + 2];
                    FMA2(acc[0], vA.x, wA.x, acc[0]); FMA2(acc[1], vA.y, wA.x, acc[1]);
                    FMA2(acc[2], vA.x, wA.y, acc[2]); FMA2(acc[3], vA.y, wA.y, acc[3]);
                    FMA2(acc[4], vB.x, wB.x, acc[4]); FMA2(acc[5], vB.y, wB.x, acc[5]);
                    FMA2(acc[6], vB.x, wB.y, acc[6]); FMA2(acc[7], vB.y, wB.y, acc[7]);
                }

                #pragma unroll
                for (int k = 0; k < 4; k++) {
                    ulonglong2 r;
                    r.x = acc[2 * k];
                    r.y = acc[2 * k + 1];
                    *reinterpret_cast<ulonglong2*>(tp + (4 * g + k) * OYP) = r;
                }
            }
        }
        __syncwarp();      // warp-local: pass B reads only this warp's tmp region

        // steal the next work item early; latency hides under pass B
        if (tid == 0) s_next = atomicAdd(&g_ctr, 1);

        // ---- Pass B: out[c][bin] = sum_x Wx[x][ox_s] * tmp[cl][oy_s][x] ----
        if (cse == 1 || cse == 2) {
            // Broadcast fast path: every px of row py reads bin (py, 7-py).
            const int cc = lane >> 3;
            const int py = lane & 7;
            const int oxs = 7 - py;

            unsigned long long a2 = 0ull;
            const float* wrow = s_WxT + oxs * WXP;
            const float* trow = s_tmp + (warp * 4 + cc) * CLP + py * OYP;

            for (int k = 0; k < ncx; k++) {
                const int x4 = xc0 + 4 * k;
                const ulonglong2 wv = *reinterpret_cast<const ulonglong2*>(wrow + x4);
                const ulonglong2 tv = *reinterpret_cast<const ulonglong2*>(trow + x4);
                FMA2(a2, tv.x, wv.x, a2);
                FMA2(a2, tv.y, wv.y, a2);
            }
            float lo, hi;
            UNPK2(lo, hi, a2);
            const float v = lo + hi;
            float4 q; q.x = v; q.y = v; q.z = v; q.w = v;

            float* __restrict__ ob =
                out + (size_t)n * (C_ * HOUT * WOUT)
                    + (size_t)(h * 32 + warp * 4 + cc) * 64 + py * 8;
            *reinterpret_cast<float4*>(ob)     = q;
            *reinterpret_cast<float4*>(ob + 4) = q;
        } else {
            // General path (cse 0 or 3): per-bin reduction.
            #pragma unroll
            for (int half = 0; half < 2; half++) {
                const int bin = half * 32 + lane;
                const int py  = bin >> 3;
                const int px  = bin & 7;
                const int oy_s = (cse == 0) ? py : 7 - py;
                const int ox_s = px;

                unsigned long long a2[4];
                #pragma unroll
                for (int ch = 0; ch < 4; ch++) a2[ch] = 0ull;

                const float* wrow = s_WxT + ox_s * WXP;
                const float* trow = s_tmp + (warp * 4) * CLP + oy_s * OYP;

                for (int k = 0; k < ncx; k++) {
                    const int x4 = xc0 + 4 * k;
                    const ulonglong2 wv =
                        *reinterpret_cast<const ulonglong2*>(wrow + x4);
                    #pragma unroll
                    for (int ch = 0; ch < 4; ch++) {
                        const ulonglong2 tv =
                            *reinterpret_cast<const ulonglong2*>(trow + ch * CLP + x4);
                        FMA2(a2[ch], tv.x, wv.x, a2[ch]);
                        FMA2(a2[ch], tv.y, wv.y, a2[ch]);
                    }
                }

                float* __restrict__ ob =
                    out + (size_t)n * (C_ * HOUT * WOUT)
                        + (size_t)(h * 32 + warp * 4) * 64 + bin;
                #pragma unroll
                for (int ch = 0; ch < 4; ch++) {
                    float lo, hi;
                    UNPK2(lo, hi, a2[ch]);
                    ob[(size_t)ch * 64] = lo + hi;
                }
            }
        }

        __syncthreads();   // publish s_next; protect smem reuse next iteration
        wid = s_next;
    }
}

extern "C" void kernel_launch(void* const* d_in, const int* in_sizes, int n_in,
                              void* d_out, int out_size) {
    const float* feats      = (const float*)d_in[0];
    const int*   batch_idxs = (const int*)d_in[1];
    const int*   starts     = (const int*)d_in[2];
    const int*   goals      = (const int*)d_in[3];
    float*       out        = (float*)d_out;

    const int N = in_sizes[1];   // number of boxes (1024)
    const int total_work = 2 * N;
    const int nblk = total_work < NBLK ? total_work : NBLK;

    prep_kernel<<<(N + 3) / 4, 256>>>(batch_idxs, starts, goals, N, nblk);

    // persistent roi kernel launched with PDL; counter + weights guarded by
    // cudaGridDependencySynchronize() in-kernel.
    cudaLaunchConfig_t cfg = {};
    cfg.gridDim  = dim3((unsigned)nblk, 1, 1);
    cfg.blockDim = dim3(256, 1, 1);
    cfg.dynamicSmemBytes = 0;
    cudaLaunchAttribute attr[1];
    attr[0].id = cudaLaunchAttributeProgrammaticStreamSerialization;
    attr[0].val.programmaticStreamSerializationAllowed = 1;
    cfg.attrs = attr;
    cfg.numAttrs = 1;
    cudaLaunchKernelEx(&cfg, roi_kernel, feats, out, total_work);
}